// round 11
// baseline (speedup 1.0000x reference)
#include <cuda_runtime.h>
#include <math.h>

#define VOCABN   10003
#define NITEMS   10000
#define PADTOK   10000
#define NPOS     512
#define SEQLEN   128
#define NTHREADS 256
#define NSPLIT   4
#define CHUNK    2500          // NITEMS / NSPLIT

typedef unsigned long long u64;

__device__ int   g_seq[NPOS];
__device__ int   g_lab[NPOS];
__device__ float g_invpb[VOCABN];
__device__ float g_pm[NPOS * NSPLIT];     // partial max per (pos, split)
__device__ float g_ps[NPOS * NSPLIT];     // partial sum per (pos, split)
__device__ float g_lablog[NPOS];          // logit at the label index

// ---------------------------------------------------------------------------
// f32x2 packed-math helpers (Blackwell; ptxas never auto-fuses these)
// ---------------------------------------------------------------------------
#define FMA2(d, a, b, c) \
    asm("fma.rn.f32x2 %0, %1, %2, %3;" : "=l"(d) : "l"(a), "l"(b), "l"(c))
#define MUL2(d, a, b) \
    asm("mul.rn.f32x2 %0, %1, %2;" : "=l"(d) : "l"(a), "l"(b))
#define PACK2(d, lo, hi) \
    asm("mov.b64 %0, {%1, %2};" : "=l"(d) : "f"(lo), "f"(hi))
#define UNPACK2(lo, hi, d) \
    asm("mov.b64 {%0, %1}, %2;" : "=f"(lo), "=f"(hi) : "l"(d))

__device__ __forceinline__ float tanh_fast(float x)
{
    float y;
    asm("tanh.approx.f32 %0, %1;" : "=f"(y) : "f"(x));
    return y;
}

// ---------------------------------------------------------------------------
// Pre-kernel: decode int64/int32 token arrays + compute 1/pop_biases
// ---------------------------------------------------------------------------
__global__ void pre_kernel(const void* __restrict__ seq_raw,
                           const void* __restrict__ lab_raw,
                           const float* __restrict__ pb)
{
    int v = blockIdx.x * NTHREADS + threadIdx.x;
    if (v < VOCABN) {
        float d = pb[v];
        g_invpb[v] = (d != 0.0f) ? (1.0f / d) : 0.0f;   // div_no_nan semantics
    }
    if (blockIdx.x == 0) {
        __shared__ int flag;
        if (threadIdx.x == 0) flag = 0;
        __syncthreads();
        const int* s32 = (const int*)seq_raw;
        const int* l32 = (const int*)lab_raw;
        for (int i = threadIdx.x; i < 256; i += NTHREADS) {
            int hs = s32[2 * i + 1];
            int hl = l32[2 * i + 1];
            if ((hs != 0 && hs != -1) || (hl != 0 && hl != -1)) atomicOr(&flag, 1);
        }
        __syncthreads();
        int is32 = flag;   // nonzero high words -> data is int32
        for (int i = threadIdx.x; i < NPOS; i += NTHREADS) {
            int idx = is32 ? i : 2 * i;
            g_seq[i] = s32[idx];
            g_lab[i] = l32[idx];
        }
    }
}

// ---------------------------------------------------------------------------
// Kernel A: one block per (position, vocab-split). Computes the 2500 logits
// of its chunk, block-local partial logsumexp (max + sum), stores partials.
//   logit = b2 + sum_j (0.5*w2_j) * (z*tanh(c(z)) + z),  z = x.W1_j + b1_j
// ---------------------------------------------------------------------------
__global__ __launch_bounds__(NTHREADS, 5)
void logits_kernel(const float* __restrict__ Tsrc,
                   const float* __restrict__ Tdst,
                   const float* __restrict__ pn,
                   const float* __restrict__ W1,
                   const float* __restrict__ b1,
                   const float* __restrict__ W2,
                   const float* __restrict__ b2)
{
    __shared__ float  slog[CHUNK];
    __shared__ float2 sw0[32], sw1[32], swr[32], sb1[32], sw2h[32];
    __shared__ float  swarp[8];
    __shared__ float  sM;

    const int bid   = blockIdx.x;
    const int pos   = bid >> 2;               // bid / NSPLIT
    const int split = bid & (NSPLIT - 1);
    const int b     = pos >> 7;
    const int t     = pos & (SEQLEN - 1);
    const int tid   = threadIdx.x;
    const int cbase = split * CHUNK;
    const int cend  = cbase + CHUNK;

    if (tid < 32) {
        float a0 = W1[tid];         sw0[tid]  = make_float2(a0, a0);
        float a1 = W1[32 + tid];    sw1[tid]  = make_float2(a1, a1);
        float ar = W1[64 + tid];    swr[tid]  = make_float2(ar, ar);
        float ab = b1[tid];         sb1[tid]  = make_float2(ab, ab);
        float a2 = 0.5f * W2[tid];  sw2h[tid] = make_float2(a2, a2);  // fold 0.5
    }

    int src = (t == 0)          ? PADTOK : max(g_seq[b * SEQLEN + t - 1], 0);
    int dst = (t == SEQLEN - 1) ? PADTOK : max(g_seq[b * SEQLEN + t + 1], 0);
    int label = g_lab[pos];

    const float* rs = Tsrc + (size_t)src * VOCABN;
    const float* rd = Tdst + (size_t)dst * VOCABN;
    const float b2v = b2[0];

    u64 C_A, C_B;
    PACK2(C_A, 0.0356774081f, 0.0356774081f);
    PACK2(C_B, 0.7978845608f, 0.7978845608f);

    __syncthreads();

    // ---- compute chunk logits: 2 packed pairs (4 items) per thread/iter ----
    for (int base = cbase; base < cend; base += NTHREADS * 4) {
        u64 x1p[2], x2p[2], x3p[2], accp[2];
        #pragma unroll
        for (int p = 0; p < 2; p++) {
            int v0 = base + (2 * p)     * NTHREADS + tid;
            int v1 = base + (2 * p + 1) * NTHREADS + tid;
            bool a0 = v0 < cend, a1 = v1 < cend;
            float ip0 = a0 ? g_invpb[v0] : 0.0f;
            float ip1 = a1 ? g_invpb[v1] : 0.0f;
            float s0 = a0 ? rs[v0] * ip0 : 0.0f;
            float s1 = a1 ? rs[v1] * ip1 : 0.0f;
            float d0 = a0 ? rd[v0] * ip0 : 0.0f;
            float d1 = a1 ? rd[v1] * ip1 : 0.0f;
            float p0 = a0 ? pn[v0] : 0.0f;
            float p1 = a1 ? pn[v1] : 0.0f;
            PACK2(x1p[p], s0, s1);
            PACK2(x2p[p], d0, d1);
            PACK2(x3p[p], p0, p1);
            PACK2(accp[p], b2v, b2v);
        }
        #pragma unroll 4
        for (int j = 0; j < 32; j++) {
            u64 w0  = *(const u64*)&sw0[j];
            u64 w1  = *(const u64*)&sw1[j];
            u64 wr  = *(const u64*)&swr[j];
            u64 bb  = *(const u64*)&sb1[j];
            u64 w2h = *(const u64*)&sw2h[j];
            #pragma unroll
            for (int p = 0; p < 2; p++) {
                u64 z, z2, w, wz, th, o;
                FMA2(z, x3p[p], wr, bb);
                FMA2(z, x2p[p], w1, z);
                FMA2(z, x1p[p], w0, z);
                MUL2(z2, z, z);
                FMA2(w, C_A, z2, C_B);
                MUL2(wz, w, z);
                float wl, wh;
                UNPACK2(wl, wh, wz);
                float tl  = tanh_fast(wl);
                float thh = tanh_fast(wh);
                PACK2(th, tl, thh);
                FMA2(o, z, th, z);            // z*tanh + z  (= 2*gelu(z))
                FMA2(accp[p], w2h, o, accp[p]);
            }
        }
        #pragma unroll
        for (int p = 0; p < 2; p++) {
            int v0 = base + (2 * p)     * NTHREADS + tid;
            int v1 = base + (2 * p + 1) * NTHREADS + tid;
            float l0, l1;
            UNPACK2(l0, l1, accp[p]);
            if (v0 < cend) slog[v0 - cbase] = l0;
            if (v1 < cend) slog[v1 - cbase] = l1;
        }
    }
    __syncthreads();

    // ---- partial logsumexp over the chunk: max ---------------------------
    float m = -3.0e38f;
    for (int v = tid; v < CHUNK; v += NTHREADS) m = fmaxf(m, slog[v]);
    #pragma unroll
    for (int o = 16; o > 0; o >>= 1) m = fmaxf(m, __shfl_xor_sync(0xffffffffu, m, o));
    if ((tid & 31) == 0) swarp[tid >> 5] = m;
    __syncthreads();
    if (tid == 0) {
        float mm = swarp[0];
        #pragma unroll
        for (int i = 1; i < 8; i++) mm = fmaxf(mm, swarp[i]);
        sM = mm;
    }
    __syncthreads();
    const float M = sM;

    // ---- partial logsumexp: sum -----------------------------------------
    float s = 0.0f;
    for (int v = tid; v < CHUNK; v += NTHREADS) s += __expf(slog[v] - M);
    #pragma unroll
    for (int o = 16; o > 0; o >>= 1) s += __shfl_xor_sync(0xffffffffu, s, o);
    __syncthreads();
    if ((tid & 31) == 0) swarp[tid >> 5] = s;
    __syncthreads();

    if (tid == 0) {
        float ss = 0.0f;
        #pragma unroll
        for (int i = 0; i < 8; i++) ss += swarp[i];
        g_pm[bid] = M;
        g_ps[bid] = ss;
        int li = min(max(label, 0), NITEMS - 1);
        if (li >= cbase && li < cend) g_lablog[pos] = slog[li - cbase];
    }
}

// ---------------------------------------------------------------------------
// Kernel B: combine partials -> cross-entropy per position
// ---------------------------------------------------------------------------
__global__ void combine_kernel(float* __restrict__ out)
{
    int pos = blockIdx.x * NTHREADS + threadIdx.x;
    if (pos >= NPOS) return;
    float m0 = g_pm[pos * NSPLIT + 0];
    float m1 = g_pm[pos * NSPLIT + 1];
    float m2 = g_pm[pos * NSPLIT + 2];
    float m3 = g_pm[pos * NSPLIT + 3];
    float M  = fmaxf(fmaxf(m0, m1), fmaxf(m2, m3));
    float S  = g_ps[pos * NSPLIT + 0] * __expf(m0 - M)
             + g_ps[pos * NSPLIT + 1] * __expf(m1 - M)
             + g_ps[pos * NSPLIT + 2] * __expf(m2 - M)
             + g_ps[pos * NSPLIT + 3] * __expf(m3 - M);
    int label  = g_lab[pos];
    bool valid = (label != -100);
    float ce   = logf(S) + M - g_lablog[pos];
    out[pos] = valid ? ce : 0.0f;
}

// ---------------------------------------------------------------------------
// Launch: inputs per metadata order
//  0 masked_sequences  1 labels  2 transitions_src  3 transitions_dst
//  4 pop_biases  5 pop_biases_norm  6 W1  7 b1  8 W2  9 b2
// ---------------------------------------------------------------------------
extern "C" void kernel_launch(void* const* d_in, const int* in_sizes, int n_in,
                              void* d_out, int out_size)
{
    const void*  seq  = d_in[0];
    const void*  lab  = d_in[1];
    const float* Tsrc = (const float*)d_in[2];
    const float* Tdst = (const float*)d_in[3];
    const float* pb   = (const float*)d_in[4];
    const float* pn   = (const float*)d_in[5];
    const float* W1   = (const float*)d_in[6];
    const float* b1   = (const float*)d_in[7];
    const float* W2   = (const float*)d_in[8];
    const float* b2   = (const float*)d_in[9];

    pre_kernel<<<(VOCABN + NTHREADS - 1) / NTHREADS, NTHREADS>>>(seq, lab, pb);
    logits_kernel<<<NPOS * NSPLIT, NTHREADS>>>(Tsrc, Tdst, pn, W1, b1, W2, b2);
    combine_kernel<<<(NPOS + NTHREADS - 1) / NTHREADS, NTHREADS>>>((float*)d_out);
}

// round 12
// speedup vs baseline: 1.0973x; 1.0973x over previous
#include <cuda_runtime.h>
#include <math.h>

#define VOCABN   10003
#define NITEMS   10000
#define PADTOK   10000
#define NPOS     512
#define SEQLEN   128
#define NTHREADS 256

typedef unsigned long long u64;

// ---------------------------------------------------------------------------
// f32x2 packed-math helpers (Blackwell; ptxas never auto-fuses these)
// ---------------------------------------------------------------------------
#define FMA2(d, a, b, c) \
    asm("fma.rn.f32x2 %0, %1, %2, %3;" : "=l"(d) : "l"(a), "l"(b), "l"(c))
#define MUL2(d, a, b) \
    asm("mul.rn.f32x2 %0, %1, %2;" : "=l"(d) : "l"(a), "l"(b))
#define PACK2(d, lo, hi) \
    asm("mov.b64 %0, {%1, %2};" : "=l"(d) : "f"(lo), "f"(hi))
#define UNPACK2(lo, hi, d) \
    asm("mov.b64 {%0, %1}, %2;" : "=f"(lo), "=f"(hi) : "l"(d))

__device__ __forceinline__ float tanh_fast(float x)
{
    float y;
    asm("tanh.approx.f32 %0, %1;" : "=f"(y) : "f"(x));
    return y;
}

__device__ __forceinline__ float rcp_fast(float x)
{
    float y;
    asm("rcp.approx.f32 %0, %1;" : "=f"(y) : "f"(x));
    return y;
}

// ---------------------------------------------------------------------------
// Fully fused kernel: one block per (b, t) position.
//  - in-block int64/int32 token decode (warp-0 ballot probe)
//  - inline 1/pop_biases via rcp.approx (+ div_no_nan zero guard)
//  - f32x2 packed MLP (4 pairs = 8 items per thread per tile)
//  - running-max fused into the logit phase; float4 sum pass
//   logit = b2 + sum_j (0.5*w2_j) * (z*tanh(c(z)) + z),  z = x.W1_j + b1_j
// ---------------------------------------------------------------------------
__global__ __launch_bounds__(NTHREADS, 4)
void bias_bert_kernel(const int* __restrict__ seq_raw,
                      const int* __restrict__ lab_raw,
                      const float* __restrict__ Tsrc,
                      const float* __restrict__ Tdst,
                      const float* __restrict__ pb,
                      const float* __restrict__ pn,
                      const float* __restrict__ W1,
                      const float* __restrict__ b1,
                      const float* __restrict__ W2,
                      const float* __restrict__ b2,
                      float* __restrict__ out)
{
    __shared__ __align__(16) float slog[NITEMS];
    __shared__ float2 sw0[32], sw1[32], swr[32], sb1[32], sw2h[32];
    __shared__ float  swarp[8];
    __shared__ float  sM;
    __shared__ int    stok[3];              // src, dst, label

    const int pos = blockIdx.x;
    const int b   = pos >> 7;
    const int t   = pos & (SEQLEN - 1);
    const int tid = threadIdx.x;

    if (tid < 32) {
        // weights (duplicated into float2 so LDS.64 yields packed operands)
        float a0 = W1[tid];         sw0[tid]  = make_float2(a0, a0);
        float a1 = W1[32 + tid];    sw1[tid]  = make_float2(a1, a1);
        float ar = W1[64 + tid];    swr[tid]  = make_float2(ar, ar);
        float ab = b1[tid];         sb1[tid]  = make_float2(ab, ab);
        float a2 = 0.5f * W2[tid];  sw2h[tid] = make_float2(a2, a2);  // fold 0.5

        // int64-vs-int32 detection: probe 32 "high words" of each array.
        // int64 data (values >= -100) has high words in {0,-1}; int32 token
        // data at those slots is a real token (all-{0,-1} prob ~ 0).
        int hs = seq_raw[2 * tid + 1];
        int hl = lab_raw[2 * tid + 1];
        unsigned bal = __ballot_sync(0xffffffffu,
                                     (hs != 0 && hs != -1) || (hl != 0 && hl != -1));
        if (tid == 0) {
            int stride = (bal != 0) ? 1 : 2;       // int32 : int64
            int base   = b * SEQLEN + t;
            int src = (t == 0)          ? PADTOK : max(seq_raw[(base - 1) * stride], 0);
            int dst = (t == SEQLEN - 1) ? PADTOK : max(seq_raw[(base + 1) * stride], 0);
            stok[0] = src;
            stok[1] = dst;
            stok[2] = lab_raw[base * stride];
        }
    }
    __syncthreads();

    const float* rs = Tsrc + (size_t)stok[0] * VOCABN;
    const float* rd = Tdst + (size_t)stok[1] * VOCABN;
    const int label = stok[2];
    const float b2v = b2[0];

    u64 C_A, C_B;
    PACK2(C_A, 0.0356774081f, 0.0356774081f);
    PACK2(C_B, 0.7978845608f, 0.7978845608f);

    float m = -3.0e38f;    // running max, fused into logit phase

    // ---- compute logits: 4 packed pairs (8 items) per thread per tile ----
    for (int base = 0; base < NITEMS; base += NTHREADS * 8) {
        u64 x1p[4], x2p[4], x3p[4], accp[4];
        #pragma unroll
        for (int p = 0; p < 4; p++) {
            int v0 = base + (2 * p)     * NTHREADS + tid;
            int v1 = base + (2 * p + 1) * NTHREADS + tid;
            bool a0 = v0 < NITEMS, a1 = v1 < NITEMS;
            float d0v = a0 ? pb[v0] : 1.0f;
            float d1v = a1 ? pb[v1] : 1.0f;
            float ip0 = (d0v != 0.0f) ? rcp_fast(d0v) : 0.0f;   // div_no_nan
            float ip1 = (d1v != 0.0f) ? rcp_fast(d1v) : 0.0f;
            float s0 = a0 ? rs[v0] * ip0 : 0.0f;
            float s1 = a1 ? rs[v1] * ip1 : 0.0f;
            float dd0 = a0 ? rd[v0] * ip0 : 0.0f;
            float dd1 = a1 ? rd[v1] * ip1 : 0.0f;
            float p0 = a0 ? pn[v0] : 0.0f;
            float p1 = a1 ? pn[v1] : 0.0f;
            PACK2(x1p[p], s0, s1);
            PACK2(x2p[p], dd0, dd1);
            PACK2(x3p[p], p0, p1);
            PACK2(accp[p], b2v, b2v);
        }
        #pragma unroll 4
        for (int j = 0; j < 32; j++) {
            u64 w0  = *(const u64*)&sw0[j];
            u64 w1  = *(const u64*)&sw1[j];
            u64 wr  = *(const u64*)&swr[j];
            u64 bb  = *(const u64*)&sb1[j];
            u64 w2h = *(const u64*)&sw2h[j];
            #pragma unroll
            for (int p = 0; p < 4; p++) {
                u64 z, z2, w, wz, th, o;
                FMA2(z, x3p[p], wr, bb);
                FMA2(z, x2p[p], w1, z);
                FMA2(z, x1p[p], w0, z);
                MUL2(z2, z, z);
                FMA2(w, C_A, z2, C_B);
                MUL2(wz, w, z);
                float wl, wh;
                UNPACK2(wl, wh, wz);
                float tl  = tanh_fast(wl);
                float thh = tanh_fast(wh);
                PACK2(th, tl, thh);
                FMA2(o, z, th, z);            // z*tanh + z  (= 2*gelu(z))
                FMA2(accp[p], w2h, o, accp[p]);
            }
        }
        #pragma unroll
        for (int p = 0; p < 4; p++) {
            int v0 = base + (2 * p)     * NTHREADS + tid;
            int v1 = base + (2 * p + 1) * NTHREADS + tid;
            float l0, l1;
            UNPACK2(l0, l1, accp[p]);
            if (v0 < NITEMS) { slog[v0] = l0; m = fmaxf(m, l0); }
            if (v1 < NITEMS) { slog[v1] = l1; m = fmaxf(m, l1); }
        }
    }

    // ---- block max (no smem re-read; m already holds thread-local max) ---
    #pragma unroll
    for (int o = 16; o > 0; o >>= 1) m = fmaxf(m, __shfl_xor_sync(0xffffffffu, m, o));
    if ((tid & 31) == 0) swarp[tid >> 5] = m;
    __syncthreads();                         // also covers slog visibility
    if (tid == 0) {
        float mm = swarp[0];
        #pragma unroll
        for (int i = 1; i < 8; i++) mm = fmaxf(mm, swarp[i]);
        sM = mm;
    }
    __syncthreads();
    const float M = sM;

    // ---- sum pass: float4 reads (NITEMS % 4 == 0) ------------------------
    float s = 0.0f;
    const float4* slog4 = (const float4*)slog;
    for (int v = tid; v < NITEMS / 4; v += NTHREADS) {
        float4 q = slog4[v];
        s += __expf(q.x - M) + __expf(q.y - M)
           + __expf(q.z - M) + __expf(q.w - M);
    }
    #pragma unroll
    for (int o = 16; o > 0; o >>= 1) s += __shfl_xor_sync(0xffffffffu, s, o);
    __syncthreads();                         // protect swarp reuse
    if ((tid & 31) == 0) swarp[tid >> 5] = s;
    __syncthreads();

    if (tid == 0) {
        float ss = 0.0f;
        #pragma unroll
        for (int i = 0; i < 8; i++) ss += swarp[i];
        bool valid = (label != -100);
        int  li = min(max(label, 0), NITEMS - 1);
        float ce = logf(ss) + M - slog[li];
        out[pos] = valid ? ce : 0.0f;
    }
}

// ---------------------------------------------------------------------------
// Launch: inputs per metadata order
//  0 masked_sequences  1 labels  2 transitions_src  3 transitions_dst
//  4 pop_biases  5 pop_biases_norm  6 W1  7 b1  8 W2  9 b2
// ---------------------------------------------------------------------------
extern "C" void kernel_launch(void* const* d_in, const int* in_sizes, int n_in,
                              void* d_out, int out_size)
{
    const int*   seq  = (const int*)d_in[0];
    const int*   lab  = (const int*)d_in[1];
    const float* Tsrc = (const float*)d_in[2];
    const float* Tdst = (const float*)d_in[3];
    const float* pb   = (const float*)d_in[4];
    const float* pn   = (const float*)d_in[5];
    const float* W1   = (const float*)d_in[6];
    const float* b1   = (const float*)d_in[7];
    const float* W2   = (const float*)d_in[8];
    const float* b2   = (const float*)d_in[9];

    bias_bert_kernel<<<NPOS, NTHREADS>>>(seq, lab, Tsrc, Tdst, pb, pn,
                                         W1, b1, W2, b2, (float*)d_out);
}